// round 2
// baseline (speedup 1.0000x reference)
#include <cuda_runtime.h>
#include <cuda_bf16.h>
#include <cstdint>

// ---------------------------------------------------------------------------
// AdversarialBlockShift
//
// Key observations (computed at runtime, not assumed):
//  * The conv kernel pk = flip(pad(param)) is sparse (here: a single delta at
//    pk[p]). We extract its nonzero taps in a tiny prep kernel; the embedding
//    kernel then does a tap-weighted gather (1 tap -> plain gather).
//  * ms = p - argmax(pk == 1.0); the id permutation is computed with the
//    general formula (cheap: B*S elements).
//
// Hardcoded problem constants (deterministic setup_inputs):
static constexpr int S_CONST   = 4096;
static constexpr int FE_START  = 5;
static constexpr int FE_LEN    = 3062;
static constexpr int ADV_LEN   = 64;
static constexpr int ML_CONST  = 995;
static constexpr int MR_CONST  = 2003;

static constexpr int MAX_TAPS = 4096;
static constexpr int MAX_B    = 8;

__device__ int   g_ntaps;
__device__ int   g_tap_off[MAX_TAPS];   // fe-relative offset (i - p)
__device__ float g_tap_w[MAX_TAPS];
__device__ int   g_ms;
__device__ int   g_a0[MAX_B];

// ---------------------------------------------------------------------------
// Prep: extract sparse taps of pk, compute ms, and per-batch a0 from the mask.
// Single block.
__global__ void prep_kernel(const float* __restrict__ param, int plen,
                            const unsigned char* __restrict__ mask,
                            int B, int S)
{
    __shared__ int s_first_one;
    __shared__ int s_a0[MAX_B];
    const int t = threadIdx.x;

    if (t == 0) {
        g_ntaps = 0;
        s_first_one = 0x7fffffff;
    }
    if (t < MAX_B) s_a0[t] = 0x7fffffff;
    __syncthreads();

    const int Kp = 2 * (ML_CONST > MR_CONST ? ML_CONST : MR_CONST) + 1;
    const int p  = Kp / 2;
    const int LP = (MR_CONST > ML_CONST) ? (MR_CONST - ML_CONST) : 0;

    // pk[i] = padded_flip(param)[i] = param[Kp-1-LP-i] (zero outside)
    for (int i = t; i < Kp; i += blockDim.x) {
        const int q = Kp - 1 - LP - i;
        const float w = (q >= 0 && q < plen) ? param[q] : 0.0f;
        if (w != 0.0f) {
            const int k = atomicAdd(&g_ntaps, 1);
            if (k < MAX_TAPS) { g_tap_off[k] = i - p; g_tap_w[k] = w; }
        }
        if (w == 1.0f) atomicMin(&s_first_one, i);
    }

    // a0[b] = first True in suffix_mask[b], else 0
    for (int b = 0; b < B && b < MAX_B; ++b) {
        for (int j = t; j < S; j += blockDim.x) {
            if (mask[b * S + j] != 0) atomicMin(&s_a0[b], j);
        }
    }
    __syncthreads();

    if (t == 0) {
        const int f = (s_first_one == 0x7fffffff) ? 0 : s_first_one;
        g_ms = p - f;
    }
    if (t < MAX_B) {
        g_a0[t] = (s_a0[t] == 0x7fffffff) ? 0 : s_a0[t];
    }
}

// ---------------------------------------------------------------------------
// out_ids: general block-shift permutation of input_ids, written as float.
__global__ void ids_kernel(const int* __restrict__ ids,
                           float* __restrict__ out, int B, int S, int L)
{
    const int i = blockIdx.x * blockDim.x + threadIdx.x;
    if (i >= B * S) return;
    const int b = i / S;
    const int j = i - b * S;

    const int a0 = g_a0[b];
    const int ns = a0 + g_ms;

    int v;
    if (j >= ns && j < ns + L) {
        int ia = j - ns;
        ia = ia < 0 ? 0 : (ia > L - 1 ? L - 1 : ia);
        v = ids[b * S + a0 + ia];
    } else {
        int q = (j < ns) ? j : (j - L);
        q = q < 0 ? 0 : (q > S - L - 1 ? S - L - 1 : q);
        const int src = q + ((q >= a0) ? L : 0);
        v = ids[b * S + src];
    }
    out[i] = (float)v;
}

// ---------------------------------------------------------------------------
// out_embeds: one block per (b, t) row; 128 threads x float4 = 512 floats.
// Outside the fe window: plain gather. Inside: tap-weighted gather
// (sparse conv over the token axis).
__global__ void __launch_bounds__(128)
embeds_kernel(const int* __restrict__ ids,
              const float* __restrict__ emb,
              float* __restrict__ out, int S, int D4)
{
    const int row = blockIdx.x;           // b * S + t
    const int b   = row / S;
    const int t   = row - b * S;
    const int d4  = threadIdx.x;          // 0 .. D4-1

    const float4* __restrict__ embv = (const float4*)emb;
    float4* __restrict__ outv = (float4*)out;
    const long base = (long)row * D4 + d4;

    const int s = t - FE_START;
    if (s < 0 || s >= FE_LEN) {
        const int tok = __ldg(&ids[row]);
        outv[base] = embv[(long)tok * D4 + d4];
        return;
    }

    const int nt = g_ntaps;
    if (nt == 1) {
        // Fast path: single tap (the common delta-kernel case).
        const int j = s + g_tap_off[0];
        const float w = g_tap_w[0];
        float4 r = make_float4(0.f, 0.f, 0.f, 0.f);
        if (j >= 0 && j < FE_LEN) {
            const int tok = __ldg(&ids[b * S + FE_START + j]);
            const float4 v = embv[(long)tok * D4 + d4];
            r = make_float4(w * v.x, w * v.y, w * v.z, w * v.w);
        }
        outv[base] = r;
        return;
    }

    float4 acc = make_float4(0.f, 0.f, 0.f, 0.f);
    for (int k = 0; k < nt; ++k) {
        const int j = s + g_tap_off[k];
        if (j >= 0 && j < FE_LEN) {
            const float w = g_tap_w[k];
            const int tok = __ldg(&ids[b * S + FE_START + j]);
            const float4 v = embv[(long)tok * D4 + d4];
            acc.x = fmaf(w, v.x, acc.x);
            acc.y = fmaf(w, v.y, acc.y);
            acc.z = fmaf(w, v.z, acc.z);
            acc.w = fmaf(w, v.w, acc.w);
        }
    }
    outv[base] = acc;
}

// ---------------------------------------------------------------------------
extern "C" void kernel_launch(void* const* d_in, const int* in_sizes, int n_in,
                              void* d_out, int out_size)
{
    const int*           input_ids = (const int*)d_in[0];
    const unsigned char* suffix_m  = (const unsigned char*)d_in[1];
    const float*         param     = (const float*)d_in[2];
    const float*         emb       = (const float*)d_in[3];

    const int BS   = in_sizes[0];          // B * S
    const int plen = in_sizes[2];          // ML + MR + 1
    const int S    = S_CONST;
    const int B    = BS / S;
    const int D    = (out_size - BS) / BS; // 512
    const int D4   = D >> 2;

    float* out_embeds = (float*)d_out;
    float* out_ids    = (float*)d_out + (long)BS * D;

    prep_kernel<<<1, 256>>>(param, plen, suffix_m, B, S);
    ids_kernel<<<(BS + 255) / 256, 256>>>(input_ids, out_ids, B, S, ADV_LEN);
    embeds_kernel<<<BS, 128>>>(input_ids, emb, out_embeds, S, D4);
}

// round 3
// speedup vs baseline: 1.4147x; 1.4147x over previous
#include <cuda_runtime.h>
#include <cuda_bf16.h>
#include <cstdint>

// ---------------------------------------------------------------------------
// AdversarialBlockShift
//
//  * pk = flip(pad(param)) is sparse; a tiny prep kernel extracts its nonzero
//    taps at runtime. The embedding kernel does a tap-weighted gather
//    (1 tap -> plain gather; dense param would still be correct).
//  * ms = p - argmax(pk == 1.0); id permutation uses the general formula.
//
// R2 -> R3: prep_kernel was latency-bound (~15us): scalar byte loads of the
// mask with MLP~1. Now: uint4-vectorized mask scan + 1024 threads, so all
// DRAM loads are in flight at once.
//
// Hardcoded problem constants (deterministic setup_inputs):
static constexpr int S_CONST   = 4096;
static constexpr int FE_START  = 5;
static constexpr int FE_LEN    = 3062;
static constexpr int ADV_LEN   = 64;
static constexpr int ML_CONST  = 995;
static constexpr int MR_CONST  = 2003;

static constexpr int MAX_TAPS = 4096;
static constexpr int MAX_B    = 8;

__device__ int   g_ntaps;
__device__ int   g_tap_off[MAX_TAPS];   // fe-relative offset (i - p)
__device__ float g_tap_w[MAX_TAPS];
__device__ int   g_ms;
__device__ int   g_a0[MAX_B];

// ---------------------------------------------------------------------------
// Prep: sparse taps of pk, ms, and per-batch a0. Single block, 1024 threads,
// fully parallel loads (uint4 mask reads -> one DRAM round trip).
__global__ void __launch_bounds__(1024)
prep_kernel(const float* __restrict__ param, int plen,
            const unsigned char* __restrict__ mask,
            int B, int S)
{
    __shared__ int s_first_one;
    __shared__ int s_ntaps;
    __shared__ int s_a0[MAX_B];
    const int t = threadIdx.x;

    if (t == 0) { s_first_one = 0x7fffffff; s_ntaps = 0; }
    if (t < MAX_B) s_a0[t] = 0x7fffffff;
    __syncthreads();

    const int Kp = 2 * (ML_CONST > MR_CONST ? ML_CONST : MR_CONST) + 1;
    const int p  = Kp / 2;
    const int LP = (MR_CONST > ML_CONST) ? (MR_CONST - ML_CONST) : 0;

    // pk[i] = padded_flip(param)[i] = param[Kp-1-LP-i] (zero outside).
    // Batch the (<=4) loads per thread first, then do the (rare) atomics.
    {
        const int iters = (Kp + blockDim.x - 1) / blockDim.x;  // 4 for 1024 thr
        float wv[8];
        int   iv[8];
        #pragma unroll
        for (int u = 0; u < 8; ++u) { wv[u] = 0.0f; iv[u] = -1; }
        for (int u = 0; u < iters && u < 8; ++u) {
            const int i = t + u * blockDim.x;
            if (i < Kp) {
                const int q = Kp - 1 - LP - i;
                iv[u] = i;
                wv[u] = (q >= 0 && q < plen) ? __ldg(&param[q]) : 0.0f;
            }
        }
        #pragma unroll
        for (int u = 0; u < 8; ++u) {
            const float w = wv[u];
            if (w != 0.0f && iv[u] >= 0) {
                const int k = atomicAdd(&s_ntaps, 1);
                if (k < MAX_TAPS) { g_tap_off[k] = iv[u] - p; g_tap_w[k] = w; }
                if (w == 1.0f) atomicMin(&s_first_one, iv[u]);
            }
        }
    }

    // a0[b] = index of first True byte in suffix_mask[b]. Vectorized 16B
    // reads; S % 16 == 0 so a uint4 never straddles a batch boundary.
    {
        const uint4* __restrict__ mv = (const uint4*)mask;
        const int nvec = (B * S) >> 4;
        for (int v = t; v < nvec; v += blockDim.x) {
            const uint4 m = mv[v];
            if (m.x | m.y | m.z | m.w) {
                const int base = v << 4;
                const int b    = base / S;
                unsigned words[4] = {m.x, m.y, m.z, m.w};
                #pragma unroll
                for (int wi = 0; wi < 4; ++wi) {
                    if (words[wi]) {
                        const int byte = (__ffs(words[wi]) - 1) >> 3;
                        atomicMin(&s_a0[b], (base + wi * 4 + byte) - b * S);
                        break;
                    }
                }
            }
        }
    }
    __syncthreads();

    if (t == 0) {
        const int f = (s_first_one == 0x7fffffff) ? 0 : s_first_one;
        g_ms = p - f;
        g_ntaps = s_ntaps;
    }
    if (t < MAX_B) {
        g_a0[t] = (s_a0[t] == 0x7fffffff) ? 0 : s_a0[t];
    }
}

// ---------------------------------------------------------------------------
// out_ids: general block-shift permutation of input_ids, written as float.
__global__ void ids_kernel(const int* __restrict__ ids,
                           float* __restrict__ out, int B, int S, int L)
{
    const int i = blockIdx.x * blockDim.x + threadIdx.x;
    if (i >= B * S) return;
    const int b = i / S;
    const int j = i - b * S;

    const int a0 = g_a0[b];
    const int ns = a0 + g_ms;

    int v;
    if (j >= ns && j < ns + L) {
        int ia = j - ns;
        ia = ia < 0 ? 0 : (ia > L - 1 ? L - 1 : ia);
        v = ids[b * S + a0 + ia];
    } else {
        int q = (j < ns) ? j : (j - L);
        q = q < 0 ? 0 : (q > S - L - 1 ? S - L - 1 : q);
        const int src = q + ((q >= a0) ? L : 0);
        v = ids[b * S + src];
    }
    out[i] = (float)v;
}

// ---------------------------------------------------------------------------
// out_embeds: one block per (b, t) row; 128 threads x float4 = 512 floats.
// Outside the fe window: plain gather. Inside: tap-weighted gather.
__global__ void __launch_bounds__(128)
embeds_kernel(const int* __restrict__ ids,
              const float* __restrict__ emb,
              float* __restrict__ out, int S, int D4)
{
    const int row = blockIdx.x;           // b * S + t
    const int b   = row / S;
    const int t   = row - b * S;
    const int d4  = threadIdx.x;          // 0 .. D4-1

    const float4* __restrict__ embv = (const float4*)emb;
    float4* __restrict__ outv = (float4*)out;
    const long base = (long)row * D4 + d4;

    const int s = t - FE_START;
    if (s < 0 || s >= FE_LEN) {
        const int tok = __ldg(&ids[row]);
        outv[base] = embv[(long)tok * D4 + d4];
        return;
    }

    const int nt = g_ntaps;
    if (nt == 1) {
        // Fast path: single tap (delta kernel -> plain scaled gather).
        const int j = s + g_tap_off[0];
        const float w = g_tap_w[0];
        float4 r = make_float4(0.f, 0.f, 0.f, 0.f);
        if (j >= 0 && j < FE_LEN) {
            const int tok = __ldg(&ids[b * S + FE_START + j]);
            const float4 v = embv[(long)tok * D4 + d4];
            r = make_float4(w * v.x, w * v.y, w * v.z, w * v.w);
        }
        outv[base] = r;
        return;
    }

    float4 acc = make_float4(0.f, 0.f, 0.f, 0.f);
    for (int k = 0; k < nt; ++k) {
        const int j = s + g_tap_off[k];
        if (j >= 0 && j < FE_LEN) {
            const float w = g_tap_w[k];
            const int tok = __ldg(&ids[b * S + FE_START + j]);
            const float4 v = embv[(long)tok * D4 + d4];
            acc.x = fmaf(w, v.x, acc.x);
            acc.y = fmaf(w, v.y, acc.y);
            acc.z = fmaf(w, v.z, acc.z);
            acc.w = fmaf(w, v.w, acc.w);
        }
    }
    outv[base] = acc;
}

// ---------------------------------------------------------------------------
extern "C" void kernel_launch(void* const* d_in, const int* in_sizes, int n_in,
                              void* d_out, int out_size)
{
    const int*           input_ids = (const int*)d_in[0];
    const unsigned char* suffix_m  = (const unsigned char*)d_in[1];
    const float*         param     = (const float*)d_in[2];
    const float*         emb       = (const float*)d_in[3];

    const int BS   = in_sizes[0];          // B * S
    const int plen = in_sizes[2];          // ML + MR + 1
    const int S    = S_CONST;
    const int B    = BS / S;
    const int D    = (out_size - BS) / BS; // 512
    const int D4   = D >> 2;

    float* out_embeds = (float*)d_out;
    float* out_ids    = (float*)d_out + (long)BS * D;

    prep_kernel<<<1, 1024>>>(param, plen, suffix_m, B, S);
    ids_kernel<<<(BS + 255) / 256, 256>>>(input_ids, out_ids, B, S, ADV_LEN);
    embeds_kernel<<<BS, 128>>>(input_ids, emb, out_embeds, S, D4);
}

// round 4
// speedup vs baseline: 1.6133x; 1.1404x over previous
#include <cuda_runtime.h>
#include <cuda_bf16.h>
#include <cstdint>

// ---------------------------------------------------------------------------
// AdversarialBlockShift
//
//  * pk = flip(pad(param)) is sparse; a tiny prep kernel extracts its nonzero
//    taps at runtime. The fused kernel does a tap-weighted gather
//    (1 tap -> plain scaled gather; dense param would still be correct).
//  * ms = p - argmax(pk == 1.0); id permutation uses the general formula.
//
// R3 -> R4: fused ids into the embeds kernel (one fewer serialized launch),
// 2 rows per 256-thread block, streaming stores (.cs) for outputs so the
// 65.5 MB embedding table stays L2-resident, gather reads via __ldcg.
//
// Hardcoded problem constants (deterministic setup_inputs):
static constexpr int S_CONST   = 4096;
static constexpr int FE_START  = 5;
static constexpr int FE_LEN    = 3062;
static constexpr int ADV_LEN   = 64;
static constexpr int ML_CONST  = 995;
static constexpr int MR_CONST  = 2003;

static constexpr int MAX_TAPS = 4096;
static constexpr int MAX_B    = 8;

__device__ int   g_ntaps;
__device__ int   g_tap_off[MAX_TAPS];   // fe-relative offset (i - p)
__device__ float g_tap_w[MAX_TAPS];
__device__ int   g_ms;
__device__ int   g_a0[MAX_B];

__device__ __forceinline__ void stcs4(float4* p, float4 v) {
    asm volatile("st.global.cs.v4.f32 [%0], {%1, %2, %3, %4};"
                 :: "l"(p), "f"(v.x), "f"(v.y), "f"(v.z), "f"(v.w) : "memory");
}
__device__ __forceinline__ float4 ldcg4(const float4* p) {
    float4 v;
    asm volatile("ld.global.cg.v4.f32 {%0, %1, %2, %3}, [%4];"
                 : "=f"(v.x), "=f"(v.y), "=f"(v.z), "=f"(v.w) : "l"(p));
    return v;
}

// ---------------------------------------------------------------------------
// Prep: sparse taps of pk, ms, and per-batch a0. Single block, 1024 threads,
// fully parallel loads (uint4 mask reads -> one DRAM round trip).
__global__ void __launch_bounds__(1024)
prep_kernel(const float* __restrict__ param, int plen,
            const unsigned char* __restrict__ mask,
            int B, int S)
{
    __shared__ int s_first_one;
    __shared__ int s_ntaps;
    __shared__ int s_a0[MAX_B];
    const int t = threadIdx.x;

    if (t == 0) { s_first_one = 0x7fffffff; s_ntaps = 0; }
    if (t < MAX_B) s_a0[t] = 0x7fffffff;
    __syncthreads();

    const int Kp = 2 * (ML_CONST > MR_CONST ? ML_CONST : MR_CONST) + 1;
    const int p  = Kp / 2;
    const int LP = (MR_CONST > ML_CONST) ? (MR_CONST - ML_CONST) : 0;

    // pk[i] = padded_flip(param)[i] = param[Kp-1-LP-i] (zero outside).
    {
        const int iters = (Kp + blockDim.x - 1) / blockDim.x;  // 4 for 1024 thr
        float wv[8];
        int   iv[8];
        #pragma unroll
        for (int u = 0; u < 8; ++u) { wv[u] = 0.0f; iv[u] = -1; }
        for (int u = 0; u < iters && u < 8; ++u) {
            const int i = t + u * blockDim.x;
            if (i < Kp) {
                const int q = Kp - 1 - LP - i;
                iv[u] = i;
                wv[u] = (q >= 0 && q < plen) ? __ldg(&param[q]) : 0.0f;
            }
        }
        #pragma unroll
        for (int u = 0; u < 8; ++u) {
            const float w = wv[u];
            if (w != 0.0f && iv[u] >= 0) {
                const int k = atomicAdd(&s_ntaps, 1);
                if (k < MAX_TAPS) { g_tap_off[k] = iv[u] - p; g_tap_w[k] = w; }
                if (w == 1.0f) atomicMin(&s_first_one, iv[u]);
            }
        }
    }

    // a0[b] = index of first True byte in suffix_mask[b]. Vectorized 16B
    // reads; S % 16 == 0 so a uint4 never straddles a batch boundary.
    {
        const uint4* __restrict__ mv = (const uint4*)mask;
        const int nvec = (B * S) >> 4;
        for (int v = t; v < nvec; v += blockDim.x) {
            const uint4 m = mv[v];
            if (m.x | m.y | m.z | m.w) {
                const int base = v << 4;
                const int b    = base / S;
                unsigned words[4] = {m.x, m.y, m.z, m.w};
                #pragma unroll
                for (int wi = 0; wi < 4; ++wi) {
                    if (words[wi]) {
                        const int byte = (__ffs(words[wi]) - 1) >> 3;
                        atomicMin(&s_a0[b], (base + wi * 4 + byte) - b * S);
                        break;
                    }
                }
            }
        }
    }
    __syncthreads();

    if (t == 0) {
        const int f = (s_first_one == 0x7fffffff) ? 0 : s_first_one;
        g_ms = p - f;
        g_ntaps = s_ntaps;
    }
    if (t < MAX_B) {
        g_a0[t] = (s_a0[t] == 0x7fffffff) ? 0 : s_a0[t];
    }
}

// ---------------------------------------------------------------------------
// Fused kernel: 2 rows per 256-thread block.
//  * lanes 0..127  -> row0 embeds, lane 0   also writes out_ids[row0]
//  * lanes 128..255-> row1 embeds, lane 128 also writes out_ids[row1]
// Outside the fe window: plain gather. Inside: tap-weighted gather.
__global__ void __launch_bounds__(256)
fused_kernel(const int* __restrict__ ids,
             const float* __restrict__ emb,
             float* __restrict__ out_embeds,
             float* __restrict__ out_ids,
             int S, int D4, int L, int Smax)
{
    const int half = threadIdx.x >> 7;            // 0 or 1
    const int d4   = threadIdx.x & 127;           // 0 .. 127
    const int row  = blockIdx.x * 2 + half;       // b * S + t
    const int b    = row / S;
    const int t    = row - b * S;

    // ---- ids permutation (one lane per row) ----
    if (d4 == 0) {
        const int a0 = g_a0[b];
        const int ns = a0 + g_ms;
        const int j  = t;
        int v;
        if (j >= ns && j < ns + L) {
            int ia = j - ns;
            ia = ia < 0 ? 0 : (ia > L - 1 ? L - 1 : ia);
            v = __ldg(&ids[b * S + a0 + ia]);
        } else {
            int q = (j < ns) ? j : (j - L);
            q = q < 0 ? 0 : (q > Smax ? Smax : q);
            const int src = q + ((q >= a0) ? L : 0);
            v = __ldg(&ids[b * S + src]);
        }
        asm volatile("st.global.cs.f32 [%0], %1;"
                     :: "l"(out_ids + row), "f"((float)v) : "memory");
    }

    // ---- embeds ----
    const float4* __restrict__ embv = (const float4*)emb;
    float4* __restrict__ outv = (float4*)out_embeds;
    float4* const dst = outv + (long)row * D4 + d4;

    const int s = t - FE_START;
    if (s < 0 || s >= FE_LEN) {
        const int tok = __ldg(&ids[row]);
        stcs4(dst, ldcg4(embv + (long)tok * D4 + d4));
        return;
    }

    const int nt = g_ntaps;
    if (nt == 1) {
        // Fast path: single tap (delta kernel -> plain scaled gather).
        const int j = s + g_tap_off[0];
        const float w = g_tap_w[0];
        float4 r = make_float4(0.f, 0.f, 0.f, 0.f);
        if (j >= 0 && j < FE_LEN) {
            const int tok = __ldg(&ids[b * S + FE_START + j]);
            const float4 v = ldcg4(embv + (long)tok * D4 + d4);
            r = make_float4(w * v.x, w * v.y, w * v.z, w * v.w);
        }
        stcs4(dst, r);
        return;
    }

    float4 acc = make_float4(0.f, 0.f, 0.f, 0.f);
    for (int k = 0; k < nt; ++k) {
        const int j = s + g_tap_off[k];
        if (j >= 0 && j < FE_LEN) {
            const float w = g_tap_w[k];
            const int tok = __ldg(&ids[b * S + FE_START + j]);
            const float4 v = ldcg4(embv + (long)tok * D4 + d4);
            acc.x = fmaf(w, v.x, acc.x);
            acc.y = fmaf(w, v.y, acc.y);
            acc.z = fmaf(w, v.z, acc.z);
            acc.w = fmaf(w, v.w, acc.w);
        }
    }
    stcs4(dst, acc);
}

// ---------------------------------------------------------------------------
extern "C" void kernel_launch(void* const* d_in, const int* in_sizes, int n_in,
                              void* d_out, int out_size)
{
    const int*           input_ids = (const int*)d_in[0];
    const unsigned char* suffix_m  = (const unsigned char*)d_in[1];
    const float*         param     = (const float*)d_in[2];
    const float*         emb       = (const float*)d_in[3];

    const int BS   = in_sizes[0];          // B * S
    const int plen = in_sizes[2];          // ML + MR + 1
    const int S    = S_CONST;
    const int B    = BS / S;
    const int D    = (out_size - BS) / BS; // 512
    const int D4   = D >> 2;

    float* out_embeds = (float*)d_out;
    float* out_ids    = (float*)d_out + (long)BS * D;

    prep_kernel<<<1, 1024>>>(param, plen, suffix_m, B, S);
    fused_kernel<<<BS / 2, 256>>>(input_ids, emb, out_embeds, out_ids,
                                  S, D4, ADV_LEN, S - ADV_LEN - 1);
}

// round 5
// speedup vs baseline: 1.7945x; 1.1123x over previous
#include <cuda_runtime.h>
#include <cuda_bf16.h>
#include <cstdint>

// ---------------------------------------------------------------------------
// AdversarialBlockShift
//
//  * pk = flip(pad(param)) is sparse; a tiny prep kernel extracts its nonzero
//    taps at runtime. The fused kernel does a tap-weighted gather
//    (1 tap -> plain scaled gather; dense param would still be correct).
//  * ms = p - argmax(pk == 1.0); id permutation uses the general formula.
//
// R4 -> R5: fused kernel was latency-bound (MLP=1/thread, DRAM 16%, issue 34%).
// Now each 128-lane group processes R=4 consecutive rows: batched independent
// token-id loads, then batched independent gathers -> MLP=4 per thread.
//
// Hardcoded problem constants (deterministic setup_inputs):
static constexpr int S_CONST   = 4096;
static constexpr int FE_START  = 5;
static constexpr int FE_LEN    = 3062;
static constexpr int ADV_LEN   = 64;
static constexpr int ML_CONST  = 995;
static constexpr int MR_CONST  = 2003;

static constexpr int R_ROWS   = 4;      // rows per 128-lane group
static constexpr int MAX_TAPS = 4096;
static constexpr int MAX_B    = 8;

__device__ int   g_ntaps;
__device__ int   g_tap_off[MAX_TAPS];   // fe-relative offset (i - p)
__device__ float g_tap_w[MAX_TAPS];
__device__ int   g_ms;
__device__ int   g_a0[MAX_B];

__device__ __forceinline__ void stcs4(float4* p, float4 v) {
    asm volatile("st.global.cs.v4.f32 [%0], {%1, %2, %3, %4};"
                 :: "l"(p), "f"(v.x), "f"(v.y), "f"(v.z), "f"(v.w) : "memory");
}
__device__ __forceinline__ float4 ldcg4(const float4* p) {
    float4 v;
    asm volatile("ld.global.cg.v4.f32 {%0, %1, %2, %3}, [%4];"
                 : "=f"(v.x), "=f"(v.y), "=f"(v.z), "=f"(v.w) : "l"(p));
    return v;
}

// ---------------------------------------------------------------------------
// Prep: sparse taps of pk, ms, and per-batch a0. Single block, 1024 threads,
// fully parallel loads (uint4 mask reads -> one DRAM round trip).
__global__ void __launch_bounds__(1024)
prep_kernel(const float* __restrict__ param, int plen,
            const unsigned char* __restrict__ mask,
            int B, int S)
{
    __shared__ int s_first_one;
    __shared__ int s_ntaps;
    __shared__ int s_a0[MAX_B];
    const int t = threadIdx.x;

    if (t == 0) { s_first_one = 0x7fffffff; s_ntaps = 0; }
    if (t < MAX_B) s_a0[t] = 0x7fffffff;
    __syncthreads();

    const int Kp = 2 * (ML_CONST > MR_CONST ? ML_CONST : MR_CONST) + 1;
    const int p  = Kp / 2;
    const int LP = (MR_CONST > ML_CONST) ? (MR_CONST - ML_CONST) : 0;

    // pk[i] = padded_flip(param)[i] = param[Kp-1-LP-i] (zero outside).
    {
        const int iters = (Kp + blockDim.x - 1) / blockDim.x;  // 4 for 1024 thr
        float wv[8];
        int   iv[8];
        #pragma unroll
        for (int u = 0; u < 8; ++u) { wv[u] = 0.0f; iv[u] = -1; }
        for (int u = 0; u < iters && u < 8; ++u) {
            const int i = t + u * blockDim.x;
            if (i < Kp) {
                const int q = Kp - 1 - LP - i;
                iv[u] = i;
                wv[u] = (q >= 0 && q < plen) ? __ldg(&param[q]) : 0.0f;
            }
        }
        #pragma unroll
        for (int u = 0; u < 8; ++u) {
            const float w = wv[u];
            if (w != 0.0f && iv[u] >= 0) {
                const int k = atomicAdd(&s_ntaps, 1);
                if (k < MAX_TAPS) { g_tap_off[k] = iv[u] - p; g_tap_w[k] = w; }
                if (w == 1.0f) atomicMin(&s_first_one, iv[u]);
            }
        }
    }

    // a0[b] = index of first True byte in suffix_mask[b]. Vectorized 16B
    // reads; S % 16 == 0 so a uint4 never straddles a batch boundary.
    {
        const uint4* __restrict__ mv = (const uint4*)mask;
        const int nvec = (B * S) >> 4;
        for (int v = t; v < nvec; v += blockDim.x) {
            const uint4 m = mv[v];
            if (m.x | m.y | m.z | m.w) {
                const int base = v << 4;
                const int b    = base / S;
                unsigned words[4] = {m.x, m.y, m.z, m.w};
                #pragma unroll
                for (int wi = 0; wi < 4; ++wi) {
                    if (words[wi]) {
                        const int byte = (__ffs(words[wi]) - 1) >> 3;
                        atomicMin(&s_a0[b], (base + wi * 4 + byte) - b * S);
                        break;
                    }
                }
            }
        }
    }
    __syncthreads();

    if (t == 0) {
        const int f = (s_first_one == 0x7fffffff) ? 0 : s_first_one;
        g_ms = p - f;
        g_ntaps = s_ntaps;
    }
    if (t < MAX_B) {
        g_a0[t] = (s_a0[t] == 0x7fffffff) ? 0 : s_a0[t];
    }
}

// ---------------------------------------------------------------------------
// Fused kernel: 256 threads = 2 groups of 128 lanes; each group handles
// R_ROWS consecutive rows (same batch: S % R_ROWS == 0, base aligned).
// Phase 1: R independent token-id loads. Phase 2: R independent gathers.
// Phase 3: scale + streaming stores. Lanes 0..R-1 also emit out_ids.
__global__ void __launch_bounds__(256)
fused_kernel(const int* __restrict__ ids,
             const float* __restrict__ emb,
             float* __restrict__ out_embeds,
             float* __restrict__ out_ids,
             int S, int D4, int L, int Smax)
{
    const int group   = threadIdx.x >> 7;                 // 0 or 1
    const int d4      = threadIdx.x & 127;                // 0 .. 127
    const int rowbase = (blockIdx.x * 2 + group) * R_ROWS;
    const int b       = rowbase / S;                      // same for all R rows
    const int tbase   = rowbase - b * S;

    // ---- ids permutation (lanes 0..R-1, one row each) ----
    if (d4 < R_ROWS) {
        const int row = rowbase + d4;
        const int j   = tbase + d4;
        const int a0  = g_a0[b];
        const int ns  = a0 + g_ms;
        int v;
        if (j >= ns && j < ns + L) {
            int ia = j - ns;
            ia = ia < 0 ? 0 : (ia > L - 1 ? L - 1 : ia);
            v = __ldg(&ids[b * S + a0 + ia]);
        } else {
            int q = (j < ns) ? j : (j - L);
            q = q < 0 ? 0 : (q > Smax ? Smax : q);
            const int src = q + ((q >= a0) ? L : 0);
            v = __ldg(&ids[b * S + src]);
        }
        asm volatile("st.global.cs.f32 [%0], %1;"
                     :: "l"(out_ids + row), "f"((float)v) : "memory");
    }

    const float4* __restrict__ embv = (const float4*)emb;
    float4* __restrict__ outv = (float4*)out_embeds;
    const int nt = g_ntaps;

    if (nt == 1) {
        const int   off0 = g_tap_off[0];
        const float w0   = g_tap_w[0];

        // Phase 1: token ids (independent)
        int   tok[R_ROWS];
        float w[R_ROWS];
        bool  valid[R_ROWS];
        #pragma unroll
        for (int r = 0; r < R_ROWS; ++r) {
            const int t = tbase + r;
            const int s = t - FE_START;
            if (s < 0 || s >= FE_LEN) {
                tok[r] = __ldg(&ids[rowbase + r]);
                w[r] = 1.0f; valid[r] = true;
            } else {
                const int j = s + off0;
                valid[r] = (j >= 0 && j < FE_LEN);
                tok[r] = valid[r] ? __ldg(&ids[b * S + FE_START + j]) : 0;
                w[r] = w0;
            }
        }
        // Phase 2: gathers (independent)
        float4 v[R_ROWS];
        #pragma unroll
        for (int r = 0; r < R_ROWS; ++r) {
            v[r] = valid[r] ? ldcg4(embv + (long)tok[r] * D4 + d4)
                            : make_float4(0.f, 0.f, 0.f, 0.f);
        }
        // Phase 3: scale + store
        #pragma unroll
        for (int r = 0; r < R_ROWS; ++r) {
            const float4 o = make_float4(w[r] * v[r].x, w[r] * v[r].y,
                                         w[r] * v[r].z, w[r] * v[r].w);
            stcs4(outv + (long)(rowbase + r) * D4 + d4, o);
        }
        return;
    }

    // General multi-tap path (correctness; rare)
    for (int r = 0; r < R_ROWS; ++r) {
        const int row = rowbase + r;
        const int t   = tbase + r;
        const int s   = t - FE_START;
        float4* const dst = outv + (long)row * D4 + d4;

        if (s < 0 || s >= FE_LEN) {
            const int tok = __ldg(&ids[row]);
            stcs4(dst, ldcg4(embv + (long)tok * D4 + d4));
            continue;
        }
        float4 acc = make_float4(0.f, 0.f, 0.f, 0.f);
        for (int k = 0; k < nt; ++k) {
            const int j = s + g_tap_off[k];
            if (j >= 0 && j < FE_LEN) {
                const float wk = g_tap_w[k];
                const int tok = __ldg(&ids[b * S + FE_START + j]);
                const float4 vv = ldcg4(embv + (long)tok * D4 + d4);
                acc.x = fmaf(wk, vv.x, acc.x);
                acc.y = fmaf(wk, vv.y, acc.y);
                acc.z = fmaf(wk, vv.z, acc.z);
                acc.w = fmaf(wk, vv.w, acc.w);
            }
        }
        stcs4(dst, acc);
    }
}

// ---------------------------------------------------------------------------
extern "C" void kernel_launch(void* const* d_in, const int* in_sizes, int n_in,
                              void* d_out, int out_size)
{
    const int*           input_ids = (const int*)d_in[0];
    const unsigned char* suffix_m  = (const unsigned char*)d_in[1];
    const float*         param     = (const float*)d_in[2];
    const float*         emb       = (const float*)d_in[3];

    const int BS   = in_sizes[0];          // B * S
    const int plen = in_sizes[2];          // ML + MR + 1
    const int S    = S_CONST;
    const int B    = BS / S;
    const int D    = (out_size - BS) / BS; // 512
    const int D4   = D >> 2;

    float* out_embeds = (float*)d_out;
    float* out_ids    = (float*)d_out + (long)BS * D;

    prep_kernel<<<1, 1024>>>(param, plen, suffix_m, B, S);
    fused_kernel<<<BS / (2 * R_ROWS), 256>>>(input_ids, emb, out_embeds,
                                             out_ids, S, D4, ADV_LEN,
                                             S - ADV_LEN - 1);
}